// round 2
// baseline (speedup 1.0000x reference)
#include <cuda_runtime.h>
#include <cstdint>

// Problem constants
#define B_      32
#define NTOK    3136
#define DIMC    768
#define DIM3    2304
#define HEADS   12
#define HD      64
#define NW      49      // num windows
#define WS      16      // queries per window (post-pool)
#define TPW     64      // tokens per window (pre-pool)
#define MTOK    784     // pooled tokens = WS*NW

// Scratch (device globals: allocation-free rule)
__device__ float g_qkv[(size_t)B_ * NTOK * DIM3];   // ~925 MB
__device__ float g_obuf[(size_t)B_ * MTOK * DIMC];  // ~77 MB

// ---------------------------------------------------------------------------
// Generic fp32 GEMM: C[M,N] = A[M,K] @ B[K,N] + bias[N]
// 128x128 block tile, 256 threads, 8x8 per-thread tile, K-step 8,
// register prefetch of next K-tile. Requires M%128==0, N%128==0, K%8==0.
// ---------------------------------------------------------------------------
__global__ __launch_bounds__(256, 2)
void gemm_bias_kernel(const float* __restrict__ A, const float* __restrict__ B,
                      const float* __restrict__ bias, float* __restrict__ C,
                      int M, int N, int K)
{
    __shared__ float As[8][132];   // padded: conflict-free transpose store
    __shared__ float Bs[8][128];

    const int tid = threadIdx.x;
    const int tx  = tid & 15;      // 0..15 -> cols {tx*4.., 64+tx*4..}
    const int ty  = tid >> 4;      // 0..15 -> rows {ty*4.., 64+ty*4..}
    const int m0  = blockIdx.y * 128;
    const int n0  = blockIdx.x * 128;

    // global load assignments
    const int a_row = tid >> 1;          // 0..127
    const int a_k   = (tid & 1) * 4;     // 0 or 4
    const int b_row = tid >> 5;          // 0..7
    const int b_col = (tid & 31) * 4;    // 0..124

    const float* Aptr = A + (size_t)(m0 + a_row) * K + a_k;
    const float* Bptr = B + (size_t)b_row * N + n0 + b_col;

    float acc[8][8];
    #pragma unroll
    for (int i = 0; i < 8; ++i)
        #pragma unroll
        for (int j = 0; j < 8; ++j) acc[i][j] = 0.f;

    // first tile
    float4 pa = *(const float4*)(Aptr);
    float4 pb = *(const float4*)(Bptr);
    As[a_k + 0][a_row] = pa.x;
    As[a_k + 1][a_row] = pa.y;
    As[a_k + 2][a_row] = pa.z;
    As[a_k + 3][a_row] = pa.w;
    *(float4*)&Bs[b_row][b_col] = pb;
    __syncthreads();

    for (int kt = 8; kt <= K; kt += 8) {
        const bool more = (kt < K);
        if (more) {
            pa = *(const float4*)(Aptr + kt);
            pb = *(const float4*)(Bptr + (size_t)kt * N);
        }
        #pragma unroll
        for (int k = 0; k < 8; ++k) {
            float4 a0 = *(const float4*)&As[k][ty * 4];
            float4 a1 = *(const float4*)&As[k][64 + ty * 4];
            float4 b0 = *(const float4*)&Bs[k][tx * 4];
            float4 b1 = *(const float4*)&Bs[k][64 + tx * 4];
            float ar[8] = {a0.x, a0.y, a0.z, a0.w, a1.x, a1.y, a1.z, a1.w};
            float br[8] = {b0.x, b0.y, b0.z, b0.w, b1.x, b1.y, b1.z, b1.w};
            #pragma unroll
            for (int i = 0; i < 8; ++i)
                #pragma unroll
                for (int j = 0; j < 8; ++j)
                    acc[i][j] = fmaf(ar[i], br[j], acc[i][j]);
        }
        if (more) {
            __syncthreads();
            As[a_k + 0][a_row] = pa.x;
            As[a_k + 1][a_row] = pa.y;
            As[a_k + 2][a_row] = pa.z;
            As[a_k + 3][a_row] = pa.w;
            *(float4*)&Bs[b_row][b_col] = pb;
            __syncthreads();
        }
    }

    // epilogue with bias, vectorized stores
    float4 bi0 = *(const float4*)&bias[n0 + tx * 4];
    float4 bi1 = *(const float4*)&bias[n0 + 64 + tx * 4];
    #pragma unroll
    for (int i = 0; i < 8; ++i) {
        int r = (i < 4) ? (m0 + ty * 4 + i) : (m0 + 64 + ty * 4 + (i - 4));
        float4 v0 = make_float4(acc[i][0] + bi0.x, acc[i][1] + bi0.y,
                                acc[i][2] + bi0.z, acc[i][3] + bi0.w);
        float4 v1 = make_float4(acc[i][4] + bi1.x, acc[i][5] + bi1.y,
                                acc[i][6] + bi1.z, acc[i][7] + bi1.w);
        *(float4*)&C[(size_t)r * N + n0 + tx * 4]      = v0;
        *(float4*)&C[(size_t)r * N + n0 + 64 + tx * 4] = v1;
    }
}

// ---------------------------------------------------------------------------
// Windowed attention. One block per (w, h, b). Window tokens are STRIDED:
// token n = t*49 + w, t in [0,64). Query pooling: qpool[qi] = max_s q[t=s*16+qi].
// Output token m = qi*49 + w, channel h*64+d.
// ---------------------------------------------------------------------------
__global__ __launch_bounds__(128)
void attn_kernel(const float* __restrict__ qkv, float* __restrict__ obuf)
{
    const int w = blockIdx.x, h = blockIdx.y, b = blockIdx.z;
    __shared__ float ks[TPW][HD + 1];
    __shared__ float vs[TPW][HD + 1];
    __shared__ float qp[WS][HD + 1];
    __shared__ float at[WS][TPW + 1];

    const int tid = threadIdx.x;
    const size_t base = (size_t)b * NTOK * DIM3;
    const int hoff = h * HD;

    // load K, V (coalesced: lanes vary d)
    #pragma unroll
    for (int i = 0; i < 32; ++i) {
        int idx = tid + i * 128;          // 0..4095
        int t = idx >> 6, d = idx & 63;
        size_t off = base + (size_t)(t * NW + w) * DIM3 + hoff + d;
        ks[t][d] = qkv[off + DIMC];       // c = 1
        vs[t][d] = qkv[off + 2 * DIMC];   // c = 2
    }
    // pooled Q: max over s of q[t = s*16 + qi]
    #pragma unroll
    for (int i = 0; i < 8; ++i) {
        int idx = tid + i * 128;          // 0..1023
        int qi = idx >> 6, d = idx & 63;
        float m = -3.0e38f;
        #pragma unroll
        for (int s = 0; s < 4; ++s) {
            int t = s * WS + qi;
            float v = qkv[base + (size_t)(t * NW + w) * DIM3 + hoff + d];
            m = fmaxf(m, v);
        }
        qp[qi][d] = m;
    }
    __syncthreads();

    // logits = scale * qp @ ks^T    [16 x 64]
    const float scale = 0.125f;           // 64^-0.5
    #pragma unroll
    for (int i = 0; i < 8; ++i) {
        int idx = tid + i * 128;
        int qi = idx >> 6, t = idx & 63;
        float s = 0.f;
        #pragma unroll
        for (int d = 0; d < HD; ++d)
            s = fmaf(qp[qi][d], ks[t][d], s);
        at[qi][t] = s * scale;
    }
    __syncthreads();

    // row softmax (64 keys). warp wj handles rows wj*4..wj*4+3.
    const int lane = tid & 31, wj = tid >> 5;
    for (int r = wj * 4; r < wj * 4 + 4; ++r) {
        float x0 = at[r][lane], x1 = at[r][lane + 32];
        float m = fmaxf(x0, x1);
        #pragma unroll
        for (int o = 16; o; o >>= 1)
            m = fmaxf(m, __shfl_xor_sync(0xffffffffu, m, o));
        float e0 = __expf(x0 - m), e1 = __expf(x1 - m);
        float s = e0 + e1;
        #pragma unroll
        for (int o = 16; o; o >>= 1)
            s += __shfl_xor_sync(0xffffffffu, s, o);
        float inv = 1.f / s;
        at[r][lane]      = e0 * inv;
        at[r][lane + 32] = e1 * inv;
    }
    __syncthreads();

    // o = attn @ vs, write to pooled token m = qi*49 + w
    #pragma unroll
    for (int i = 0; i < 8; ++i) {
        int idx = tid + i * 128;
        int qi = idx >> 6, d = idx & 63;
        float s = 0.f;
        #pragma unroll
        for (int t = 0; t < TPW; ++t)
            s = fmaf(at[qi][t], vs[t][d], s);
        int m = qi * NW + w;
        obuf[((size_t)b * MTOK + m) * DIMC + hoff + d] = s;
    }
}

// ---------------------------------------------------------------------------
extern "C" void kernel_launch(void* const* d_in, const int* in_sizes, int n_in,
                              void* d_out, int out_size)
{
    const float* x     = (const float*)d_in[0];
    const float* Wqkv  = (const float*)d_in[1];
    const float* bqkv  = (const float*)d_in[2];
    const float* Wproj = (const float*)d_in[3];
    const float* bproj = (const float*)d_in[4];
    float* out = (float*)d_out;

    float *qkvp = nullptr, *obufp = nullptr;
    cudaGetSymbolAddress((void**)&qkvp, g_qkv);
    cudaGetSymbolAddress((void**)&obufp, g_obuf);

    // 1) QKV projection: [100352,768] @ [768,2304] + bqkv
    {
        dim3 grid(DIM3 / 128, (B_ * NTOK) / 128);   // (18, 784)
        gemm_bias_kernel<<<grid, 256>>>(x, Wqkv, bqkv, qkvp,
                                        B_ * NTOK, DIM3, DIMC);
    }
    // 2) windowed attention with query max-pool
    {
        dim3 grid(NW, HEADS, B_);                   // (49, 12, 32)
        attn_kernel<<<grid, 128>>>(qkvp, obufp);
    }
    // 3) output projection: [25088,768] @ [768,768] + bproj
    {
        dim3 grid(DIMC / 128, (B_ * MTOK) / 128);   // (6, 196)
        gemm_bias_kernel<<<grid, 256>>>(obufp, Wproj, bproj, out,
                                        B_ * MTOK, DIMC, DIMC);
    }
}

// round 5
// speedup vs baseline: 2.0299x; 2.0299x over previous
#include <cuda_runtime.h>
#include <cuda_bf16.h>
#include <cstdint>

// Problem constants
#define B_      32
#define NTOK    3136
#define DIMC    768
#define DIM3    2304
#define HEADS   12
#define HD      64
#define NW      49
#define WS      16
#define TPW     64
#define MTOK    784
#define KDIM    768

#define NELEM_X   ((size_t)B_ * NTOK * DIMC)
#define NELEM_O   ((size_t)B_ * MTOK * DIMC)
#define WQT_ELEMS ((size_t)DIM3 * DIMC)
#define WPT_ELEMS ((size_t)DIMC * DIMC)

// Scratch (device globals: allocation-free rule)
__device__ float          g_qkv[(size_t)B_ * NTOK * DIM3];
__device__ __nv_bfloat16  g_xhi[NELEM_X];
__device__ __nv_bfloat16  g_xlo[NELEM_X];
__device__ __nv_bfloat16  g_ohi[NELEM_O];
__device__ __nv_bfloat16  g_olo[NELEM_O];
__device__ __nv_bfloat16  g_whi[WQT_ELEMS + WPT_ELEMS];   // [N][K] transposed
__device__ __nv_bfloat16  g_wlo[WQT_ELEMS + WPT_ELEMS];

// ---------------------------------------------------------------------------
// PTX helpers (base sm_103 target only: mma.sync / ldmatrix / cp.async)
// ---------------------------------------------------------------------------
__device__ __forceinline__ uint32_t smem_u32(const void* p) {
    uint32_t a;
    asm("{ .reg .u64 t; cvta.to.shared.u64 t, %1; cvt.u32.u64 %0, t; }" : "=r"(a) : "l"(p));
    return a;
}
#define CP_ASYNC16(dst, src) \
    asm volatile("cp.async.cg.shared.global [%0], [%1], 16;" :: "r"(dst), "l"(src))
#define CP_COMMIT() asm volatile("cp.async.commit_group;" ::: "memory")
#define CP_WAIT1()  asm volatile("cp.async.wait_group 1;" ::: "memory")

#define LDSM4(r, addr) \
    asm volatile("ldmatrix.sync.aligned.m8n8.x4.shared.b16 {%0,%1,%2,%3}, [%4];" \
                 : "=r"((r)[0]), "=r"((r)[1]), "=r"((r)[2]), "=r"((r)[3]) : "r"(addr))

#define MMA_BF16(c, a, b0, b1) \
    asm volatile("mma.sync.aligned.m16n8k16.row.col.f32.bf16.bf16.f32 " \
                 "{%0,%1,%2,%3}, {%4,%5,%6,%7}, {%8,%9}, {%0,%1,%2,%3};" \
                 : "+f"((c)[0]), "+f"((c)[1]), "+f"((c)[2]), "+f"((c)[3]) \
                 : "r"((a)[0]), "r"((a)[1]), "r"((a)[2]), "r"((a)[3]), \
                   "r"(b0), "r"(b1))

// ---------------------------------------------------------------------------
// 3x-bf16 split GEMM via mma.sync: C[M,N] = A[M,K] @ W[K,N] + bias
// W passed transposed [N][K]. Tile 128x128, 8 warps (warp tile 32x64), KC=32,
// cp.async double-buffered. Row stride 80B (64B data + 16B pad): conflict-free
// ldmatrix (bank = 20*r mod 32, distinct within each 8-lane phase).
// ---------------------------------------------------------------------------
#define TILE_MN  128
#define KC       32
#define ASTR     80                      // bytes per 32-bf16 row
#define HALF_OFF 10240                   // 128 rows * 80B  (hi block size)
#define STG_B    20480                   // B matrix offset within stage
#define STG_BYTES 40960
#define GEMM_SMEM (2 * STG_BYTES)        // 81920

__device__ __forceinline__ void load_stage(
    const __nv_bfloat16* __restrict__ Ahi, const __nv_bfloat16* __restrict__ Alo,
    const __nv_bfloat16* __restrict__ Bhi, const __nv_bfloat16* __restrict__ Blo,
    int m0, int n0, int kt, int K, uint32_t buf, int tid)
{
    #pragma unroll
    for (int i = 0; i < 8; ++i) {
        int idx = tid + i * 256;          // 0..2047
        int mat = idx >> 10;              // 0 = A, 1 = B
        int c   = idx & 1023;
        int wl  = c >> 9;                 // 0 = hi, 1 = lo
        int r   = (c >> 2) & 127;
        int g   = c & 3;
        const __nv_bfloat16* base =
            mat ? (wl ? Blo : Bhi) : (wl ? Alo : Ahi);
        const __nv_bfloat16* src =
            base + (size_t)((mat ? n0 : m0) + r) * K + kt + g * 8;
        uint32_t dst = buf + mat * STG_B + wl * HALF_OFF + r * ASTR + g * 16;
        CP_ASYNC16(dst, src);
    }
    CP_COMMIT();
}

__global__ __launch_bounds__(256, 2)
void gemm3x_kernel(const __nv_bfloat16* __restrict__ Ahi, const __nv_bfloat16* __restrict__ Alo,
                   const __nv_bfloat16* __restrict__ Bhi, const __nv_bfloat16* __restrict__ Blo,
                   const float* __restrict__ bias, float* __restrict__ C,
                   int M, int N, int K)
{
    extern __shared__ char smem[];
    const uint32_t sb = smem_u32(smem);
    const int tid = threadIdx.x, wid = tid >> 5, lane = tid & 31;
    const int wm = wid & 3, wn = wid >> 2;        // warp grid 4(M) x 2(N)
    const int m0 = blockIdx.y * TILE_MN;
    const int n0 = blockIdx.x * TILE_MN;

    float acc[2][8][4];
    #pragma unroll
    for (int mt = 0; mt < 2; ++mt)
        #pragma unroll
        for (int nt = 0; nt < 8; ++nt)
            #pragma unroll
            for (int j = 0; j < 4; ++j) acc[mt][nt][j] = 0.f;

    const int NST = K / KC;               // 24
    load_stage(Ahi, Alo, Bhi, Blo, m0, n0, 0, K, sb, tid);
    load_stage(Ahi, Alo, Bhi, Blo, m0, n0, KC, K, sb + STG_BYTES, tid);

    // precomputed intra-tile ldmatrix offsets
    const uint32_t a_off = (uint32_t)((wm * 32 + (lane & 15)) * ASTR + (lane >> 4) * 16);
    const uint32_t b_off = (uint32_t)((wn * 64 + (lane & 7) + ((lane & 16) ? 8 : 0)) * ASTR
                                      + ((lane >> 3) & 1) * 16);

    for (int s = 0; s < NST; ++s) {
        const uint32_t buf = sb + (s & 1) * STG_BYTES;
        CP_WAIT1();
        __syncthreads();

        #pragma unroll
        for (int j = 0; j < 2; ++j) {     // two k16 steps per stage
            uint32_t aHi[2][4], aLo[2][4];
            #pragma unroll
            for (int mt = 0; mt < 2; ++mt) {
                uint32_t aa = buf + a_off + mt * (16 * ASTR) + j * 32;
                LDSM4(aHi[mt], aa);
                LDSM4(aLo[mt], aa + HALF_OFF);
            }
            #pragma unroll
            for (int p = 0; p < 4; ++p) { // 4 pairs of n-tiles
                uint32_t ba = buf + STG_B + b_off + p * (16 * ASTR) + j * 32;
                uint32_t bh[4], bl[4];
                LDSM4(bh, ba);
                LDSM4(bl, ba + HALF_OFF);
                #pragma unroll
                for (int mt = 0; mt < 2; ++mt) {
                    MMA_BF16(acc[mt][2 * p],     aHi[mt], bh[0], bh[1]);
                    MMA_BF16(acc[mt][2 * p],     aHi[mt], bl[0], bl[1]);
                    MMA_BF16(acc[mt][2 * p],     aLo[mt], bh[0], bh[1]);
                    MMA_BF16(acc[mt][2 * p + 1], aHi[mt], bh[2], bh[3]);
                    MMA_BF16(acc[mt][2 * p + 1], aHi[mt], bl[2], bl[3]);
                    MMA_BF16(acc[mt][2 * p + 1], aLo[mt], bh[2], bh[3]);
                }
            }
        }
        __syncthreads();                  // all reads of this buffer done
        if (s + 2 < NST)
            load_stage(Ahi, Alo, Bhi, Blo, m0, n0, (s + 2) * KC, K, buf, tid);
        else
            CP_COMMIT();                  // empty group keeps wait counts aligned
    }

    // Epilogue: direct register -> gmem with bias (float2 stores)
    #pragma unroll
    for (int nt = 0; nt < 8; ++nt) {
        const int col = n0 + wn * 64 + nt * 8 + (lane & 3) * 2;
        const float2 bi = *(const float2*)&bias[col];
        #pragma unroll
        for (int mt = 0; mt < 2; ++mt) {
            const int row = m0 + wm * 32 + mt * 16 + (lane >> 2);
            float2 v0 = make_float2(acc[mt][nt][0] + bi.x, acc[mt][nt][1] + bi.y);
            float2 v1 = make_float2(acc[mt][nt][2] + bi.x, acc[mt][nt][3] + bi.y);
            *(float2*)&C[(size_t)row * N + col]       = v0;
            *(float2*)&C[(size_t)(row + 8) * N + col] = v1;
        }
    }
}

// ---------------------------------------------------------------------------
// x -> (hi, lo) bf16 split
// ---------------------------------------------------------------------------
__global__ void xconv_kernel(const float* __restrict__ X, __nv_bfloat16* __restrict__ hi,
                             __nv_bfloat16* __restrict__ lo, int n4)
{
    int i = blockIdx.x * blockDim.x + threadIdx.x;
    if (i >= n4) return;
    float4 v = ((const float4*)X)[i];
    float a[4] = {v.x, v.y, v.z, v.w};
    __nv_bfloat16 h[4], l[4];
    #pragma unroll
    for (int j = 0; j < 4; ++j) {
        h[j] = __float2bfloat16(a[j]);
        l[j] = __float2bfloat16(a[j] - __bfloat162float(h[j]));
    }
    ((__nv_bfloat162*)hi)[2 * i]     = __halves2bfloat162(h[0], h[1]);
    ((__nv_bfloat162*)hi)[2 * i + 1] = __halves2bfloat162(h[2], h[3]);
    ((__nv_bfloat162*)lo)[2 * i]     = __halves2bfloat162(l[0], l[1]);
    ((__nv_bfloat162*)lo)[2 * i + 1] = __halves2bfloat162(l[2], l[3]);
}

// ---------------------------------------------------------------------------
// W[K][N] -> Wt hi/lo [N][K] (transpose + split)
// ---------------------------------------------------------------------------
__global__ void wconv_kernel(const float* __restrict__ W, __nv_bfloat16* __restrict__ hi,
                             __nv_bfloat16* __restrict__ lo, int K, int N)
{
    __shared__ float t[32][33];
    const int nb = blockIdx.x * 32, kb = blockIdx.y * 32;
    const int tx = threadIdx.x, ty = threadIdx.y;   // block (32, 8)
    #pragma unroll
    for (int j = 0; j < 4; ++j)
        t[ty + 8 * j][tx] = W[(size_t)(kb + ty + 8 * j) * N + nb + tx];
    __syncthreads();
    #pragma unroll
    for (int j = 0; j < 4; ++j) {
        int n = nb + ty + 8 * j, k = kb + tx;
        float v = t[tx][ty + 8 * j];
        __nv_bfloat16 h = __float2bfloat16(v);
        __nv_bfloat16 l = __float2bfloat16(v - __bfloat162float(h));
        hi[(size_t)n * K + k] = h;
        lo[(size_t)n * K + k] = l;
    }
}

// ---------------------------------------------------------------------------
// Windowed attention (fp32 math), outputs bf16 hi/lo for the proj GEMM
// ---------------------------------------------------------------------------
__global__ __launch_bounds__(128)
void attn_kernel(const float* __restrict__ qkv,
                 __nv_bfloat16* __restrict__ ohi, __nv_bfloat16* __restrict__ olo)
{
    const int w = blockIdx.x, h = blockIdx.y, b = blockIdx.z;
    __shared__ float ks[TPW][HD + 1];
    __shared__ float vs[TPW][HD + 1];
    __shared__ float qp[WS][HD + 1];
    __shared__ float at[WS][TPW + 1];

    const int tid = threadIdx.x;
    const size_t base = (size_t)b * NTOK * DIM3;
    const int hoff = h * HD;

    #pragma unroll
    for (int i = 0; i < 32; ++i) {
        int idx = tid + i * 128;
        int t = idx >> 6, d = idx & 63;
        size_t off = base + (size_t)(t * NW + w) * DIM3 + hoff + d;
        ks[t][d] = qkv[off + DIMC];
        vs[t][d] = qkv[off + 2 * DIMC];
    }
    #pragma unroll
    for (int i = 0; i < 8; ++i) {
        int idx = tid + i * 128;
        int qi = idx >> 6, d = idx & 63;
        float m = -3.0e38f;
        #pragma unroll
        for (int s = 0; s < 4; ++s) {
            int t = s * WS + qi;
            float v = qkv[base + (size_t)(t * NW + w) * DIM3 + hoff + d];
            m = fmaxf(m, v);
        }
        qp[qi][d] = m;
    }
    __syncthreads();

    const float scale = 0.125f;
    #pragma unroll
    for (int i = 0; i < 8; ++i) {
        int idx = tid + i * 128;
        int qi = idx >> 6, t = idx & 63;
        float s = 0.f;
        #pragma unroll
        for (int d = 0; d < HD; ++d)
            s = fmaf(qp[qi][d], ks[t][d], s);
        at[qi][t] = s * scale;
    }
    __syncthreads();

    const int lane = tid & 31, wj = tid >> 5;
    for (int r = wj * 4; r < wj * 4 + 4; ++r) {
        float x0 = at[r][lane], x1 = at[r][lane + 32];
        float m = fmaxf(x0, x1);
        #pragma unroll
        for (int o = 16; o; o >>= 1)
            m = fmaxf(m, __shfl_xor_sync(0xffffffffu, m, o));
        float e0 = __expf(x0 - m), e1 = __expf(x1 - m);
        float s = e0 + e1;
        #pragma unroll
        for (int o = 16; o; o >>= 1)
            s += __shfl_xor_sync(0xffffffffu, s, o);
        float inv = 1.f / s;
        at[r][lane]      = e0 * inv;
        at[r][lane + 32] = e1 * inv;
    }
    __syncthreads();

    #pragma unroll
    for (int i = 0; i < 8; ++i) {
        int idx = tid + i * 128;
        int qi = idx >> 6, d = idx & 63;
        float s = 0.f;
        #pragma unroll
        for (int t = 0; t < TPW; ++t)
            s = fmaf(at[qi][t], vs[t][d], s);
        int m = qi * NW + w;
        size_t oi = ((size_t)b * MTOK + m) * DIMC + hoff + d;
        __nv_bfloat16 hh = __float2bfloat16(s);
        __nv_bfloat16 ll = __float2bfloat16(s - __bfloat162float(hh));
        ohi[oi] = hh;
        olo[oi] = ll;
    }
}

// ---------------------------------------------------------------------------
extern "C" void kernel_launch(void* const* d_in, const int* in_sizes, int n_in,
                              void* d_out, int out_size)
{
    const float* x     = (const float*)d_in[0];
    const float* Wqkv  = (const float*)d_in[1];
    const float* bqkv  = (const float*)d_in[2];
    const float* Wproj = (const float*)d_in[3];
    const float* bproj = (const float*)d_in[4];
    float* out = (float*)d_out;

    float* qkvp = nullptr;
    __nv_bfloat16 *xhi, *xlo, *ohi, *olo, *whi, *wlo;
    cudaGetSymbolAddress((void**)&qkvp, g_qkv);
    cudaGetSymbolAddress((void**)&xhi, g_xhi);
    cudaGetSymbolAddress((void**)&xlo, g_xlo);
    cudaGetSymbolAddress((void**)&ohi, g_ohi);
    cudaGetSymbolAddress((void**)&olo, g_olo);
    cudaGetSymbolAddress((void**)&whi, g_whi);
    cudaGetSymbolAddress((void**)&wlo, g_wlo);

    cudaFuncSetAttribute(gemm3x_kernel,
                         cudaFuncAttributeMaxDynamicSharedMemorySize, GEMM_SMEM);

    // 0a) split x into bf16 hi/lo
    {
        int n4 = (int)(NELEM_X / 4);
        xconv_kernel<<<n4 / 256, 256>>>(x, xhi, xlo, n4);
    }
    // 0b) transpose + split weights
    {
        dim3 b(32, 8);
        wconv_kernel<<<dim3(DIM3 / 32, DIMC / 32), b>>>(Wqkv, whi, wlo, DIMC, DIM3);
        wconv_kernel<<<dim3(DIMC / 32, DIMC / 32), b>>>(Wproj, whi + WQT_ELEMS,
                                                        wlo + WQT_ELEMS, DIMC, DIMC);
    }
    // 1) QKV projection: [100352,768] @ [768,2304] + bqkv  (HMMA, 3x bf16)
    {
        dim3 grid(DIM3 / TILE_MN, (B_ * NTOK) / TILE_MN);   // (18, 784)
        gemm3x_kernel<<<grid, 256, GEMM_SMEM>>>(xhi, xlo, whi, wlo, bqkv, qkvp,
                                                B_ * NTOK, DIM3, KDIM);
    }
    // 2) windowed attention with query max-pool
    {
        dim3 grid(NW, HEADS, B_);
        attn_kernel<<<grid, 128>>>(qkvp, ohi, olo);
    }
    // 3) output projection: [25088,768] @ [768,768] + bproj
    {
        dim3 grid(DIMC / TILE_MN, (B_ * MTOK) / TILE_MN);   // (6, 196)
        gemm3x_kernel<<<grid, 256, GEMM_SMEM>>>(ohi, olo, whi + WQT_ELEMS, wlo + WQT_ELEMS,
                                                bproj, out, B_ * MTOK, DIMC, KDIM);
    }
}

// round 6
// speedup vs baseline: 2.1436x; 1.0560x over previous
#include <cuda_runtime.h>
#include <cuda_bf16.h>
#include <cstdint>

// Problem constants
#define B_      32
#define NTOK    3136
#define DIMC    768
#define DIM3    2304
#define HEADS   12
#define HD      64
#define NW      49
#define WS      16
#define TPW     64
#define MTOK    784
#define KDIM    768

#define NELEM_X   ((size_t)B_ * NTOK * DIMC)
#define NELEM_O   ((size_t)B_ * MTOK * DIMC)
#define WQT_ELEMS ((size_t)DIM3 * DIMC)
#define WPT_ELEMS ((size_t)DIMC * DIMC)

// Scratch (device globals: allocation-free rule)
__device__ float          g_qkv[(size_t)B_ * NTOK * DIM3];
__device__ __nv_bfloat16  g_xhi[NELEM_X];
__device__ __nv_bfloat16  g_xlo[NELEM_X];
__device__ __nv_bfloat16  g_ohi[NELEM_O];
__device__ __nv_bfloat16  g_olo[NELEM_O];
__device__ __nv_bfloat16  g_whi[WQT_ELEMS + WPT_ELEMS];   // [N][K] transposed
__device__ __nv_bfloat16  g_wlo[WQT_ELEMS + WPT_ELEMS];

// ---------------------------------------------------------------------------
// PTX helpers (base sm_103 target: mma.sync / ldmatrix / cp.async)
// ---------------------------------------------------------------------------
__device__ __forceinline__ uint32_t smem_u32(const void* p) {
    uint32_t a;
    asm("{ .reg .u64 t; cvta.to.shared.u64 t, %1; cvt.u32.u64 %0, t; }" : "=r"(a) : "l"(p));
    return a;
}
#define CP_ASYNC16(dst, src) \
    asm volatile("cp.async.cg.shared.global [%0], [%1], 16;" :: "r"(dst), "l"(src))
#define CP_COMMIT() asm volatile("cp.async.commit_group;" ::: "memory")
#define CP_WAIT1()  asm volatile("cp.async.wait_group 1;" ::: "memory")

#define LDSM4(r, addr) \
    asm volatile("ldmatrix.sync.aligned.m8n8.x4.shared.b16 {%0,%1,%2,%3}, [%4];" \
                 : "=r"((r)[0]), "=r"((r)[1]), "=r"((r)[2]), "=r"((r)[3]) : "r"(addr))

#define MMA_BF16(c, a, b0, b1) \
    asm volatile("mma.sync.aligned.m16n8k16.row.col.f32.bf16.bf16.f32 " \
                 "{%0,%1,%2,%3}, {%4,%5,%6,%7}, {%8,%9}, {%0,%1,%2,%3};" \
                 : "+f"((c)[0]), "+f"((c)[1]), "+f"((c)[2]), "+f"((c)[3]) \
                 : "r"((a)[0]), "r"((a)[1]), "r"((a)[2]), "r"((a)[3]), \
                   "r"(b0), "r"(b1))

// ---------------------------------------------------------------------------
// 3x-bf16 split GEMM via mma.sync: C[M,N] = A[M,K] @ W[K,N] + bias
// W passed transposed [N][K]. Tile 128x128, 8 warps (warp tile 32x64), KC=32.
// SMEM layout: per matrix, row r holds [hi 32bf16 | lo 32bf16] = 128B,
// chunk j (16B) stored at (j ^ (r&7))*16 -> conflict-free ldmatrix, no pad.
// 3-stage cp.async ring, ONE __syncthreads per stage.
// MMA schedule: pass-major (hh, lh, hl) so consecutive MMAs never share an
// accumulator (reuse distance 16).
// ---------------------------------------------------------------------------
#define TILE_MN   128
#define KC        32
#define MAT_BYTES 16384                 // 128 rows * 128B
#define STG_BYTES 32768                 // A + B
#define NSTAGE    3
#define GEMM_SMEM (NSTAGE * STG_BYTES)  // 98304

__device__ __forceinline__ void load_stage(
    const __nv_bfloat16* __restrict__ Ahi, const __nv_bfloat16* __restrict__ Alo,
    const __nv_bfloat16* __restrict__ Bhi, const __nv_bfloat16* __restrict__ Blo,
    int m0, int n0, int kt, int K, uint32_t buf, int tid)
{
    #pragma unroll
    for (int i = 0; i < 8; ++i) {
        int idx = tid + i * 256;          // 0..2047
        int mat = idx >> 10;              // 0 = A, 1 = B
        int c   = idx & 1023;
        int r   = c >> 3;                 // row 0..127
        int j   = c & 7;                  // 16B chunk: 0-3 hi, 4-7 lo
        int wl  = j >> 2, g = j & 3;
        const __nv_bfloat16* base = mat ? (wl ? Blo : Bhi) : (wl ? Alo : Ahi);
        const __nv_bfloat16* src  = base + (size_t)((mat ? n0 : m0) + r) * K + kt + g * 8;
        uint32_t dst = buf + mat * MAT_BYTES + r * 128 + ((j ^ (r & 7)) * 16);
        CP_ASYNC16(dst, src);
    }
    CP_COMMIT();
}

__global__ __launch_bounds__(256, 2)
void gemm3x_kernel(const __nv_bfloat16* __restrict__ Ahi, const __nv_bfloat16* __restrict__ Alo,
                   const __nv_bfloat16* __restrict__ Bhi, const __nv_bfloat16* __restrict__ Blo,
                   const float* __restrict__ bias, float* __restrict__ C,
                   int M, int N, int K)
{
    extern __shared__ char smem[];
    const uint32_t sb = smem_u32(smem);
    const int tid = threadIdx.x, wid = tid >> 5, lane = tid & 31;
    const int wm = wid & 3, wn = wid >> 2;        // warp grid 4(M) x 2(N)
    const int m0 = blockIdx.y * TILE_MN;
    const int n0 = blockIdx.x * TILE_MN;

    float acc[2][8][4];
    #pragma unroll
    for (int mt = 0; mt < 2; ++mt)
        #pragma unroll
        for (int nt = 0; nt < 8; ++nt)
            #pragma unroll
            for (int j = 0; j < 4; ++j) acc[mt][nt][j] = 0.f;

    const int NST = K / KC;               // 24
    load_stage(Ahi, Alo, Bhi, Blo, m0, n0, 0,  K, sb,             tid);
    load_stage(Ahi, Alo, Bhi, Blo, m0, n0, KC, K, sb + STG_BYTES, tid);

    // per-lane ldmatrix geometry
    const int a_row  = wm * 32 + (lane & 15);             // + mt*16
    const int a_csel = lane >> 4;                         // 0/1
    const int a_sx   = a_row & 7;
    const uint32_t a_base = (uint32_t)a_row * 128;
    const int b_row  = wn * 64 + (lane & 7) + ((lane & 16) ? 8 : 0);  // + p*16
    const int b_csel = (lane >> 3) & 1;
    const int b_sx   = b_row & 7;
    const uint32_t b_base = MAT_BYTES + (uint32_t)b_row * 128;

    for (int s = 0; s < NST; ++s) {
        const uint32_t buf = sb + (uint32_t)(s % NSTAGE) * STG_BYTES;
        CP_WAIT1();
        __syncthreads();
        if (s + 2 < NST)
            load_stage(Ahi, Alo, Bhi, Blo, m0, n0, (s + 2) * KC, K,
                       sb + (uint32_t)((s + 2) % NSTAGE) * STG_BYTES, tid);
        else
            CP_COMMIT();                  // empty group keeps wait counts aligned

        #pragma unroll
        for (int j = 0; j < 2; ++j) {     // two k16 steps per stage
            uint32_t aHi[2][4], aLo[2][4], bb[4][4];
            #pragma unroll
            for (int mt = 0; mt < 2; ++mt) {
                uint32_t ra = buf + a_base + mt * (16 * 128);
                LDSM4(aHi[mt], ra + (((2 * j + a_csel)     ^ a_sx) * 16));
                LDSM4(aLo[mt], ra + (((2 * j + a_csel + 4) ^ a_sx) * 16));
            }
            #pragma unroll
            for (int p = 0; p < 4; ++p) {
                uint32_t rb = buf + b_base + p * (16 * 128);
                LDSM4(bb[p], rb + (((2 * j + b_csel) ^ b_sx) * 16));
            }
            // pass hh: 16 MMAs, all-distinct accumulators
            #pragma unroll
            for (int p = 0; p < 4; ++p)
                #pragma unroll
                for (int mt = 0; mt < 2; ++mt) {
                    MMA_BF16(acc[mt][2 * p],     aHi[mt], bb[p][0], bb[p][1]);
                    MMA_BF16(acc[mt][2 * p + 1], aHi[mt], bb[p][2], bb[p][3]);
                }
            // pass lh
            #pragma unroll
            for (int p = 0; p < 4; ++p)
                #pragma unroll
                for (int mt = 0; mt < 2; ++mt) {
                    MMA_BF16(acc[mt][2 * p],     aLo[mt], bb[p][0], bb[p][1]);
                    MMA_BF16(acc[mt][2 * p + 1], aLo[mt], bb[p][2], bb[p][3]);
                }
            // reload B as lo, pass hl
            #pragma unroll
            for (int p = 0; p < 4; ++p) {
                uint32_t rb = buf + b_base + p * (16 * 128);
                LDSM4(bb[p], rb + (((2 * j + b_csel + 4) ^ b_sx) * 16));
            }
            #pragma unroll
            for (int p = 0; p < 4; ++p)
                #pragma unroll
                for (int mt = 0; mt < 2; ++mt) {
                    MMA_BF16(acc[mt][2 * p],     aHi[mt], bb[p][0], bb[p][1]);
                    MMA_BF16(acc[mt][2 * p + 1], aHi[mt], bb[p][2], bb[p][3]);
                }
        }
        // no trailing sync: next stage's barrier fences buffer reuse
    }

    // Epilogue: direct register -> gmem with bias (float2 stores)
    #pragma unroll
    for (int nt = 0; nt < 8; ++nt) {
        const int col = n0 + wn * 64 + nt * 8 + (lane & 3) * 2;
        const float2 bi = *(const float2*)&bias[col];
        #pragma unroll
        for (int mt = 0; mt < 2; ++mt) {
            const int row = m0 + wm * 32 + mt * 16 + (lane >> 2);
            float2 v0 = make_float2(acc[mt][nt][0] + bi.x, acc[mt][nt][1] + bi.y);
            float2 v1 = make_float2(acc[mt][nt][2] + bi.x, acc[mt][nt][3] + bi.y);
            *(float2*)&C[(size_t)row * N + col]       = v0;
            *(float2*)&C[(size_t)(row + 8) * N + col] = v1;
        }
    }
}

// ---------------------------------------------------------------------------
// x -> (hi, lo) bf16 split
// ---------------------------------------------------------------------------
__global__ void xconv_kernel(const float* __restrict__ X, __nv_bfloat16* __restrict__ hi,
                             __nv_bfloat16* __restrict__ lo, int n4)
{
    int i = blockIdx.x * blockDim.x + threadIdx.x;
    if (i >= n4) return;
    float4 v = ((const float4*)X)[i];
    float a[4] = {v.x, v.y, v.z, v.w};
    __nv_bfloat16 h[4], l[4];
    #pragma unroll
    for (int j = 0; j < 4; ++j) {
        h[j] = __float2bfloat16(a[j]);
        l[j] = __float2bfloat16(a[j] - __bfloat162float(h[j]));
    }
    ((__nv_bfloat162*)hi)[2 * i]     = __halves2bfloat162(h[0], h[1]);
    ((__nv_bfloat162*)hi)[2 * i + 1] = __halves2bfloat162(h[2], h[3]);
    ((__nv_bfloat162*)lo)[2 * i]     = __halves2bfloat162(l[0], l[1]);
    ((__nv_bfloat162*)lo)[2 * i + 1] = __halves2bfloat162(l[2], l[3]);
}

// ---------------------------------------------------------------------------
// W[K][N] -> Wt hi/lo [N][K] (transpose + split)
// ---------------------------------------------------------------------------
__global__ void wconv_kernel(const float* __restrict__ W, __nv_bfloat16* __restrict__ hi,
                             __nv_bfloat16* __restrict__ lo, int K, int N)
{
    __shared__ float t[32][33];
    const int nb = blockIdx.x * 32, kb = blockIdx.y * 32;
    const int tx = threadIdx.x, ty = threadIdx.y;   // block (32, 8)
    #pragma unroll
    for (int j = 0; j < 4; ++j)
        t[ty + 8 * j][tx] = W[(size_t)(kb + ty + 8 * j) * N + nb + tx];
    __syncthreads();
    #pragma unroll
    for (int j = 0; j < 4; ++j) {
        int n = nb + ty + 8 * j, k = kb + tx;
        float v = t[tx][ty + 8 * j];
        __nv_bfloat16 h = __float2bfloat16(v);
        __nv_bfloat16 l = __float2bfloat16(v - __bfloat162float(h));
        hi[(size_t)n * K + k] = h;
        lo[(size_t)n * K + k] = l;
    }
}

// ---------------------------------------------------------------------------
// Windowed attention (fp32 math), outputs bf16 hi/lo for the proj GEMM
// ---------------------------------------------------------------------------
__global__ __launch_bounds__(128)
void attn_kernel(const float* __restrict__ qkv,
                 __nv_bfloat16* __restrict__ ohi, __nv_bfloat16* __restrict__ olo)
{
    const int w = blockIdx.x, h = blockIdx.y, b = blockIdx.z;
    __shared__ float ks[TPW][HD + 1];
    __shared__ float vs[TPW][HD + 1];
    __shared__ float qp[WS][HD + 1];
    __shared__ float at[WS][TPW + 1];

    const int tid = threadIdx.x;
    const size_t base = (size_t)b * NTOK * DIM3;
    const int hoff = h * HD;

    #pragma unroll
    for (int i = 0; i < 32; ++i) {
        int idx = tid + i * 128;
        int t = idx >> 6, d = idx & 63;
        size_t off = base + (size_t)(t * NW + w) * DIM3 + hoff + d;
        ks[t][d] = qkv[off + DIMC];
        vs[t][d] = qkv[off + 2 * DIMC];
    }
    #pragma unroll
    for (int i = 0; i < 8; ++i) {
        int idx = tid + i * 128;
        int qi = idx >> 6, d = idx & 63;
        float m = -3.0e38f;
        #pragma unroll
        for (int s = 0; s < 4; ++s) {
            int t = s * WS + qi;
            float v = qkv[base + (size_t)(t * NW + w) * DIM3 + hoff + d];
            m = fmaxf(m, v);
        }
        qp[qi][d] = m;
    }
    __syncthreads();

    const float scale = 0.125f;
    #pragma unroll
    for (int i = 0; i < 8; ++i) {
        int idx = tid + i * 128;
        int qi = idx >> 6, t = idx & 63;
        float s = 0.f;
        #pragma unroll
        for (int d = 0; d < HD; ++d)
            s = fmaf(qp[qi][d], ks[t][d], s);
        at[qi][t] = s * scale;
    }
    __syncthreads();

    const int lane = tid & 31, wj = tid >> 5;
    for (int r = wj * 4; r < wj * 4 + 4; ++r) {
        float x0 = at[r][lane], x1 = at[r][lane + 32];
        float m = fmaxf(x0, x1);
        #pragma unroll
        for (int o = 16; o; o >>= 1)
            m = fmaxf(m, __shfl_xor_sync(0xffffffffu, m, o));
        float e0 = __expf(x0 - m), e1 = __expf(x1 - m);
        float s = e0 + e1;
        #pragma unroll
        for (int o = 16; o; o >>= 1)
            s += __shfl_xor_sync(0xffffffffu, s, o);
        float inv = 1.f / s;
        at[r][lane]      = e0 * inv;
        at[r][lane + 32] = e1 * inv;
    }
    __syncthreads();

    #pragma unroll
    for (int i = 0; i < 8; ++i) {
        int idx = tid + i * 128;
        int qi = idx >> 6, d = idx & 63;
        float s = 0.f;
        #pragma unroll
        for (int t = 0; t < TPW; ++t)
            s = fmaf(at[qi][t], vs[t][d], s);
        int m = qi * NW + w;
        size_t oi = ((size_t)b * MTOK + m) * DIMC + hoff + d;
        __nv_bfloat16 hh = __float2bfloat16(s);
        __nv_bfloat16 ll = __float2bfloat16(s - __bfloat162float(hh));
        ohi[oi] = hh;
        olo[oi] = ll;
    }
}

// ---------------------------------------------------------------------------
extern "C" void kernel_launch(void* const* d_in, const int* in_sizes, int n_in,
                              void* d_out, int out_size)
{
    const float* x     = (const float*)d_in[0];
    const float* Wqkv  = (const float*)d_in[1];
    const float* bqkv  = (const float*)d_in[2];
    const float* Wproj = (const float*)d_in[3];
    const float* bproj = (const float*)d_in[4];
    float* out = (float*)d_out;

    float* qkvp = nullptr;
    __nv_bfloat16 *xhi, *xlo, *ohi, *olo, *whi, *wlo;
    cudaGetSymbolAddress((void**)&qkvp, g_qkv);
    cudaGetSymbolAddress((void**)&xhi, g_xhi);
    cudaGetSymbolAddress((void**)&xlo, g_xlo);
    cudaGetSymbolAddress((void**)&ohi, g_ohi);
    cudaGetSymbolAddress((void**)&olo, g_olo);
    cudaGetSymbolAddress((void**)&whi, g_whi);
    cudaGetSymbolAddress((void**)&wlo, g_wlo);

    cudaFuncSetAttribute(gemm3x_kernel,
                         cudaFuncAttributeMaxDynamicSharedMemorySize, GEMM_SMEM);

    // 0a) split x into bf16 hi/lo
    {
        int n4 = (int)(NELEM_X / 4);
        xconv_kernel<<<n4 / 256, 256>>>(x, xhi, xlo, n4);
    }
    // 0b) transpose + split weights
    {
        dim3 b(32, 8);
        wconv_kernel<<<dim3(DIM3 / 32, DIMC / 32), b>>>(Wqkv, whi, wlo, DIMC, DIM3);
        wconv_kernel<<<dim3(DIMC / 32, DIMC / 32), b>>>(Wproj, whi + WQT_ELEMS,
                                                        wlo + WQT_ELEMS, DIMC, DIMC);
    }
    // 1) QKV projection: [100352,768] @ [768,2304] + bqkv  (HMMA, 3x bf16)
    {
        dim3 grid(DIM3 / TILE_MN, (B_ * NTOK) / TILE_MN);   // (18, 784)
        gemm3x_kernel<<<grid, 256, GEMM_SMEM>>>(xhi, xlo, whi, wlo, bqkv, qkvp,
                                                B_ * NTOK, DIM3, KDIM);
    }
    // 2) windowed attention with query max-pool
    {
        dim3 grid(NW, HEADS, B_);
        attn_kernel<<<grid, 128>>>(qkvp, ohi, olo);
    }
    // 3) output projection: [25088,768] @ [768,768] + bproj
    {
        dim3 grid(DIMC / TILE_MN, (B_ * MTOK) / TILE_MN);   // (6, 196)
        gemm3x_kernel<<<grid, 256, GEMM_SMEM>>>(ohi, olo, whi + WQT_ELEMS, wlo + WQT_ELEMS,
                                                bproj, out, B_ * MTOK, DIMC, KDIM);
    }
}

// round 7
// speedup vs baseline: 4.6235x; 2.1569x over previous
#include <cuda_runtime.h>
#include <cuda_fp16.h>
#include <cstdint>

// Problem constants
#define B_      32
#define NTOK    3136
#define DIMC    768
#define DIM3    2304
#define HEADS   12
#define HD      64
#define NW      49
#define WS      16
#define TPW     64
#define MTOK    784
#define KDIM    768

#define NELEM_X   ((size_t)B_ * NTOK * DIMC)
#define NELEM_O   ((size_t)B_ * MTOK * DIMC)
#define WQT_ELEMS ((size_t)DIM3 * DIMC)
#define WPT_ELEMS ((size_t)DIMC * DIMC)

// Scratch (device globals: allocation-free rule)
__device__ float  g_qkv[(size_t)B_ * NTOK * DIM3];
__device__ __half g_xh[NELEM_X];
__device__ __half g_oh[NELEM_O];
__device__ __half g_wt[WQT_ELEMS + WPT_ELEMS];   // [N][K] transposed, fp16

// ---------------------------------------------------------------------------
// PTX helpers (base sm_103 target: mma.sync / ldmatrix / cp.async)
// ---------------------------------------------------------------------------
__device__ __forceinline__ uint32_t smem_u32(const void* p) {
    uint32_t a;
    asm("{ .reg .u64 t; cvta.to.shared.u64 t, %1; cvt.u32.u64 %0, t; }" : "=r"(a) : "l"(p));
    return a;
}
#define CP_ASYNC16(dst, src) \
    asm volatile("cp.async.cg.shared.global [%0], [%1], 16;" :: "r"(dst), "l"(src))
#define CP_COMMIT() asm volatile("cp.async.commit_group;" ::: "memory")
#define CP_WAIT1()  asm volatile("cp.async.wait_group 1;" ::: "memory")

#define LDSM4(r, addr) \
    asm volatile("ldmatrix.sync.aligned.m8n8.x4.shared.b16 {%0,%1,%2,%3}, [%4];" \
                 : "=r"((r)[0]), "=r"((r)[1]), "=r"((r)[2]), "=r"((r)[3]) : "r"(addr))

#define MMA_F16(c, a, b0, b1) \
    asm volatile("mma.sync.aligned.m16n8k16.row.col.f32.f16.f16.f32 " \
                 "{%0,%1,%2,%3}, {%4,%5,%6,%7}, {%8,%9}, {%0,%1,%2,%3};" \
                 : "+f"((c)[0]), "+f"((c)[1]), "+f"((c)[2]), "+f"((c)[3]) \
                 : "r"((a)[0]), "r"((a)[1]), "r"((a)[2]), "r"((a)[3]), \
                   "r"(b0), "r"(b1))

// ---------------------------------------------------------------------------
// Single-pass fp16 GEMM via mma.sync: C[M,N] = A[M,K] @ W[K,N] + bias
// W passed transposed [N][K]. Tile 128x128, 8 warps (warp tile 32x64), KC=64.
// SMEM: row r = 64 fp16 = 128B, 16B chunk j stored at (j ^ (r&7))*16 ->
// conflict-free ldmatrix, no padding. 3-stage cp.async ring, ONE barrier/stage.
// ---------------------------------------------------------------------------
#define TILE_MN   128
#define KC        64
#define MAT_BYTES 16384                 // 128 rows * 128B
#define STG_BYTES 32768                 // A + B
#define NSTAGE    3
#define GEMM_SMEM (NSTAGE * STG_BYTES)  // 98304

__device__ __forceinline__ void load_stage(
    const __half* __restrict__ A, const __half* __restrict__ Bt,
    int m0, int n0, int kt, int K, uint32_t buf, int tid)
{
    #pragma unroll
    for (int i = 0; i < 8; ++i) {
        int idx = tid + i * 256;          // 0..2047
        int mat = idx >> 10;              // 0 = A, 1 = B
        int c   = idx & 1023;
        int r   = c >> 3;                 // row 0..127
        int g   = c & 7;                  // 16B chunk (8 fp16)
        const __half* src = (mat ? Bt : A)
                          + (size_t)((mat ? n0 : m0) + r) * K + kt + g * 8;
        uint32_t dst = buf + mat * MAT_BYTES + r * 128 + ((g ^ (r & 7)) * 16);
        CP_ASYNC16(dst, src);
    }
    CP_COMMIT();
}

__global__ __launch_bounds__(256, 2)
void gemm_f16_kernel(const __half* __restrict__ A, const __half* __restrict__ Bt,
                     const float* __restrict__ bias, float* __restrict__ C,
                     int M, int N, int K)
{
    extern __shared__ char smem[];
    const uint32_t sb = smem_u32(smem);
    const int tid = threadIdx.x, wid = tid >> 5, lane = tid & 31;
    const int wm = wid & 3, wn = wid >> 2;        // warp grid 4(M) x 2(N)
    const int m0 = blockIdx.y * TILE_MN;
    const int n0 = blockIdx.x * TILE_MN;

    float acc[2][8][4];
    #pragma unroll
    for (int mt = 0; mt < 2; ++mt)
        #pragma unroll
        for (int nt = 0; nt < 8; ++nt)
            #pragma unroll
            for (int j = 0; j < 4; ++j) acc[mt][nt][j] = 0.f;

    const int NST = K / KC;               // 12
    load_stage(A, Bt, m0, n0, 0,  K, sb,             tid);
    load_stage(A, Bt, m0, n0, KC, K, sb + STG_BYTES, tid);

    // per-lane ldmatrix geometry (identical to proven bf16 version)
    const int a_row  = wm * 32 + (lane & 15);             // + mt*16
    const int a_csel = lane >> 4;                         // 0/1 (k-half)
    const int a_sx   = a_row & 7;
    const uint32_t a_base = (uint32_t)a_row * 128;
    const int b_row  = wn * 64 + (lane & 7) + ((lane & 16) ? 8 : 0);  // + p*16
    const int b_csel = (lane >> 3) & 1;
    const int b_sx   = b_row & 7;
    const uint32_t b_base = MAT_BYTES + (uint32_t)b_row * 128;

    for (int s = 0; s < NST; ++s) {
        const uint32_t buf = sb + (uint32_t)(s % NSTAGE) * STG_BYTES;
        CP_WAIT1();
        __syncthreads();
        if (s + 2 < NST)
            load_stage(A, Bt, m0, n0, (s + 2) * KC, K,
                       sb + (uint32_t)((s + 2) % NSTAGE) * STG_BYTES, tid);
        else
            CP_COMMIT();                  // empty group keeps wait counts aligned

        #pragma unroll
        for (int j = 0; j < 4; ++j) {     // four k16 steps per stage
            uint32_t af[2][4], bf[4][4];
            #pragma unroll
            for (int mt = 0; mt < 2; ++mt)
                LDSM4(af[mt], buf + a_base + mt * (16 * 128)
                              + (((2 * j + a_csel) ^ a_sx) * 16));
            #pragma unroll
            for (int p = 0; p < 4; ++p)
                LDSM4(bf[p], buf + b_base + p * (16 * 128)
                             + (((2 * j + b_csel) ^ b_sx) * 16));
            // 16 MMAs, all-distinct accumulators (reuse distance 16)
            #pragma unroll
            for (int p = 0; p < 4; ++p)
                #pragma unroll
                for (int mt = 0; mt < 2; ++mt) {
                    MMA_F16(acc[mt][2 * p],     af[mt], bf[p][0], bf[p][1]);
                    MMA_F16(acc[mt][2 * p + 1], af[mt], bf[p][2], bf[p][3]);
                }
        }
        // no trailing sync: next stage's barrier fences buffer reuse
    }

    // Epilogue: direct register -> gmem with bias (float2 stores)
    #pragma unroll
    for (int nt = 0; nt < 8; ++nt) {
        const int col = n0 + wn * 64 + nt * 8 + (lane & 3) * 2;
        const float2 bi = *(const float2*)&bias[col];
        #pragma unroll
        for (int mt = 0; mt < 2; ++mt) {
            const int row = m0 + wm * 32 + mt * 16 + (lane >> 2);
            float2 v0 = make_float2(acc[mt][nt][0] + bi.x, acc[mt][nt][1] + bi.y);
            float2 v1 = make_float2(acc[mt][nt][2] + bi.x, acc[mt][nt][3] + bi.y);
            *(float2*)&C[(size_t)row * N + col]       = v0;
            *(float2*)&C[(size_t)(row + 8) * N + col] = v1;
        }
    }
}

// ---------------------------------------------------------------------------
// x -> fp16
// ---------------------------------------------------------------------------
__global__ void xconv_kernel(const float* __restrict__ X, __half* __restrict__ H, int n4)
{
    int i = blockIdx.x * blockDim.x + threadIdx.x;
    if (i >= n4) return;
    float4 v = ((const float4*)X)[i];
    __half2 h0 = __floats2half2_rn(v.x, v.y);
    __half2 h1 = __floats2half2_rn(v.z, v.w);
    ((__half2*)H)[2 * i]     = h0;
    ((__half2*)H)[2 * i + 1] = h1;
}

// ---------------------------------------------------------------------------
// W[K][N] -> W^T fp16 [N][K]
// ---------------------------------------------------------------------------
__global__ void wconv_kernel(const float* __restrict__ W, __half* __restrict__ Wt,
                             int K, int N)
{
    __shared__ float t[32][33];
    const int nb = blockIdx.x * 32, kb = blockIdx.y * 32;
    const int tx = threadIdx.x, ty = threadIdx.y;   // block (32, 8)
    #pragma unroll
    for (int j = 0; j < 4; ++j)
        t[ty + 8 * j][tx] = W[(size_t)(kb + ty + 8 * j) * N + nb + tx];
    __syncthreads();
    #pragma unroll
    for (int j = 0; j < 4; ++j) {
        int n = nb + ty + 8 * j, k = kb + tx;
        Wt[(size_t)n * K + k] = __float2half_rn(t[tx][ty + 8 * j]);
    }
}

// ---------------------------------------------------------------------------
// Windowed attention (fp32 math), outputs fp16 o for the proj GEMM
// ---------------------------------------------------------------------------
__global__ __launch_bounds__(128)
void attn_kernel(const float* __restrict__ qkv, __half* __restrict__ oh)
{
    const int w = blockIdx.x, h = blockIdx.y, b = blockIdx.z;
    __shared__ float ks[TPW][HD + 1];
    __shared__ float vs[TPW][HD + 1];
    __shared__ float qp[WS][HD + 1];
    __shared__ float at[WS][TPW + 1];

    const int tid = threadIdx.x;
    const size_t base = (size_t)b * NTOK * DIM3;
    const int hoff = h * HD;

    #pragma unroll
    for (int i = 0; i < 32; ++i) {
        int idx = tid + i * 128;
        int t = idx >> 6, d = idx & 63;
        size_t off = base + (size_t)(t * NW + w) * DIM3 + hoff + d;
        ks[t][d] = qkv[off + DIMC];
        vs[t][d] = qkv[off + 2 * DIMC];
    }
    #pragma unroll
    for (int i = 0; i < 8; ++i) {
        int idx = tid + i * 128;
        int qi = idx >> 6, d = idx & 63;
        float m = -3.0e38f;
        #pragma unroll
        for (int s = 0; s < 4; ++s) {
            int t = s * WS + qi;
            float v = qkv[base + (size_t)(t * NW + w) * DIM3 + hoff + d];
            m = fmaxf(m, v);
        }
        qp[qi][d] = m;
    }
    __syncthreads();

    const float scale = 0.125f;
    #pragma unroll
    for (int i = 0; i < 8; ++i) {
        int idx = tid + i * 128;
        int qi = idx >> 6, t = idx & 63;
        float s = 0.f;
        #pragma unroll
        for (int d = 0; d < HD; ++d)
            s = fmaf(qp[qi][d], ks[t][d], s);
        at[qi][t] = s * scale;
    }
    __syncthreads();

    const int lane = tid & 31, wj = tid >> 5;
    for (int r = wj * 4; r < wj * 4 + 4; ++r) {
        float x0 = at[r][lane], x1 = at[r][lane + 32];
        float m = fmaxf(x0, x1);
        #pragma unroll
        for (int o = 16; o; o >>= 1)
            m = fmaxf(m, __shfl_xor_sync(0xffffffffu, m, o));
        float e0 = __expf(x0 - m), e1 = __expf(x1 - m);
        float s = e0 + e1;
        #pragma unroll
        for (int o = 16; o; o >>= 1)
            s += __shfl_xor_sync(0xffffffffu, s, o);
        float inv = 1.f / s;
        at[r][lane]      = e0 * inv;
        at[r][lane + 32] = e1 * inv;
    }
    __syncthreads();

    #pragma unroll
    for (int i = 0; i < 8; ++i) {
        int idx = tid + i * 128;
        int qi = idx >> 6, d = idx & 63;
        float s = 0.f;
        #pragma unroll
        for (int t = 0; t < TPW; ++t)
            s = fmaf(at[qi][t], vs[t][d], s);
        int m = qi * NW + w;
        oh[((size_t)b * MTOK + m) * DIMC + hoff + d] = __float2half_rn(s);
    }
}

// ---------------------------------------------------------------------------
extern "C" void kernel_launch(void* const* d_in, const int* in_sizes, int n_in,
                              void* d_out, int out_size)
{
    const float* x     = (const float*)d_in[0];
    const float* Wqkv  = (const float*)d_in[1];
    const float* bqkv  = (const float*)d_in[2];
    const float* Wproj = (const float*)d_in[3];
    const float* bproj = (const float*)d_in[4];
    float* out = (float*)d_out;

    float* qkvp = nullptr;
    __half *xh, *oh, *wt;
    cudaGetSymbolAddress((void**)&qkvp, g_qkv);
    cudaGetSymbolAddress((void**)&xh, g_xh);
    cudaGetSymbolAddress((void**)&oh, g_oh);
    cudaGetSymbolAddress((void**)&wt, g_wt);

    cudaFuncSetAttribute(gemm_f16_kernel,
                         cudaFuncAttributeMaxDynamicSharedMemorySize, GEMM_SMEM);

    // 0a) x -> fp16
    {
        int n4 = (int)(NELEM_X / 4);
        xconv_kernel<<<n4 / 256, 256>>>(x, xh, n4);
    }
    // 0b) transpose weights -> fp16 [N][K]
    {
        dim3 b(32, 8);
        wconv_kernel<<<dim3(DIM3 / 32, DIMC / 32), b>>>(Wqkv, wt, DIMC, DIM3);
        wconv_kernel<<<dim3(DIMC / 32, DIMC / 32), b>>>(Wproj, wt + WQT_ELEMS,
                                                        DIMC, DIMC);
    }
    // 1) QKV projection: [100352,768] @ [768,2304] + bqkv  (fp16 HMMA)
    {
        dim3 grid(DIM3 / TILE_MN, (B_ * NTOK) / TILE_MN);   // (18, 784)
        gemm_f16_kernel<<<grid, 256, GEMM_SMEM>>>(xh, wt, bqkv, qkvp,
                                                  B_ * NTOK, DIM3, KDIM);
    }
    // 2) windowed attention with query max-pool
    {
        dim3 grid(NW, HEADS, B_);
        attn_kernel<<<grid, 128>>>(qkvp, oh);
    }
    // 3) output projection: [25088,768] @ [768,768] + bproj
    {
        dim3 grid(DIMC / TILE_MN, (B_ * MTOK) / TILE_MN);   // (6, 196)
        gemm_f16_kernel<<<grid, 256, GEMM_SMEM>>>(oh, wt + WQT_ELEMS,
                                                  bproj, out, B_ * MTOK, DIMC, KDIM);
    }
}

// round 8
// speedup vs baseline: 4.6540x; 1.0066x over previous
#include <cuda_runtime.h>
#include <cuda_fp16.h>
#include <cstdint>

// Problem constants
#define B_      32
#define NTOK    3136
#define DIMC    768
#define DIM3    2304
#define HEADS   12
#define HD      64
#define NW      49
#define WS      16
#define TPW     64
#define MTOK    784
#define KDIM    768

#define NELEM_X   ((size_t)B_ * NTOK * DIMC)
#define NELEM_O   ((size_t)B_ * MTOK * DIMC)
#define WQT_ELEMS ((size_t)DIM3 * DIMC)
#define WPT_ELEMS ((size_t)DIMC * DIMC)

// Scratch (device globals: allocation-free rule)
__device__ __half g_qkv[(size_t)B_ * NTOK * DIM3];   // fp16 qkv (462 MB)
__device__ __half g_xh[NELEM_X];
__device__ __half g_oh[NELEM_O];
__device__ __half g_wt[WQT_ELEMS + WPT_ELEMS];       // [N][K] transposed, fp16

// ---------------------------------------------------------------------------
// PTX helpers (base sm_103 target: mma.sync / ldmatrix / cp.async)
// ---------------------------------------------------------------------------
__device__ __forceinline__ uint32_t smem_u32(const void* p) {
    uint32_t a;
    asm("{ .reg .u64 t; cvta.to.shared.u64 t, %1; cvt.u32.u64 %0, t; }" : "=r"(a) : "l"(p));
    return a;
}
#define CP_ASYNC16(dst, src) \
    asm volatile("cp.async.cg.shared.global [%0], [%1], 16;" :: "r"(dst), "l"(src))
#define CP_COMMIT() asm volatile("cp.async.commit_group;" ::: "memory")
#define CP_WAIT1()  asm volatile("cp.async.wait_group 1;" ::: "memory")

#define LDSM4(r, addr) \
    asm volatile("ldmatrix.sync.aligned.m8n8.x4.shared.b16 {%0,%1,%2,%3}, [%4];" \
                 : "=r"((r)[0]), "=r"((r)[1]), "=r"((r)[2]), "=r"((r)[3]) : "r"(addr))

#define MMA_F16(c, a, b0, b1) \
    asm volatile("mma.sync.aligned.m16n8k16.row.col.f32.f16.f16.f32 " \
                 "{%0,%1,%2,%3}, {%4,%5,%6,%7}, {%8,%9}, {%0,%1,%2,%3};" \
                 : "+f"((c)[0]), "+f"((c)[1]), "+f"((c)[2]), "+f"((c)[3]) \
                 : "r"((a)[0]), "r"((a)[1]), "r"((a)[2]), "r"((a)[3]), \
                   "r"(b0), "r"(b1))

// ---------------------------------------------------------------------------
// Single-pass fp16 GEMM via mma.sync: C[M,N] = A[M,K] @ W[K,N] + bias
// W transposed [N][K]. Tile 128x128, 8 warps (warp tile 32x64), KC=64.
// SMEM: row r = 64 fp16 = 128B, 16B chunk g at (g ^ (r&7))*16 (conflict-free,
// no pad). 3-stage cp.async ring, one barrier/stage. B-LDSM software-
// pipelined against MMA groups. OUT_HALF selects fp16 vs fp32 C.
// ---------------------------------------------------------------------------
#define TILE_MN   128
#define KC        64
#define MAT_BYTES 16384                 // 128 rows * 128B
#define STG_BYTES 32768                 // A + B
#define NSTAGE    3
#define GEMM_SMEM (NSTAGE * STG_BYTES)  // 98304

__device__ __forceinline__ void load_stage(
    const __half* __restrict__ A, const __half* __restrict__ Bt,
    int m0, int n0, int kt, int K, uint32_t buf, int tid)
{
    #pragma unroll
    for (int i = 0; i < 8; ++i) {
        int idx = tid + i * 256;          // 0..2047
        int mat = idx >> 10;              // 0 = A, 1 = B
        int c   = idx & 1023;
        int r   = c >> 3;                 // row 0..127
        int g   = c & 7;                  // 16B chunk (8 fp16)
        const __half* src = (mat ? Bt : A)
                          + (size_t)((mat ? n0 : m0) + r) * K + kt + g * 8;
        uint32_t dst = buf + mat * MAT_BYTES + r * 128 + ((g ^ (r & 7)) * 16);
        CP_ASYNC16(dst, src);
    }
    CP_COMMIT();
}

template <int OUT_HALF>
__global__ __launch_bounds__(256, 2)
void gemm_f16_kernel(const __half* __restrict__ A, const __half* __restrict__ Bt,
                     const float* __restrict__ bias, void* __restrict__ Cv,
                     int M, int N, int K)
{
    extern __shared__ char smem[];
    const uint32_t sb = smem_u32(smem);
    const int tid = threadIdx.x, wid = tid >> 5, lane = tid & 31;
    const int wm = wid & 3, wn = wid >> 2;        // warp grid 4(M) x 2(N)
    const int m0 = blockIdx.y * TILE_MN;
    const int n0 = blockIdx.x * TILE_MN;

    float acc[2][8][4];
    #pragma unroll
    for (int mt = 0; mt < 2; ++mt)
        #pragma unroll
        for (int nt = 0; nt < 8; ++nt)
            #pragma unroll
            for (int j = 0; j < 4; ++j) acc[mt][nt][j] = 0.f;

    const int NST = K / KC;               // 12
    load_stage(A, Bt, m0, n0, 0,  K, sb,             tid);
    load_stage(A, Bt, m0, n0, KC, K, sb + STG_BYTES, tid);

    // per-lane ldmatrix geometry
    const int a_row  = wm * 32 + (lane & 15);             // + mt*16
    const int a_csel = lane >> 4;                         // 0/1 (k-half)
    const int a_sx   = a_row & 7;
    const uint32_t a_base = (uint32_t)a_row * 128;
    const int b_row  = wn * 64 + (lane & 7) + ((lane & 16) ? 8 : 0);  // + p*16
    const int b_csel = (lane >> 3) & 1;
    const int b_sx   = b_row & 7;
    const uint32_t b_base = MAT_BYTES + (uint32_t)b_row * 128;

    for (int s = 0; s < NST; ++s) {
        const uint32_t buf = sb + (uint32_t)(s % NSTAGE) * STG_BYTES;
        CP_WAIT1();
        __syncthreads();
        if (s + 2 < NST)
            load_stage(A, Bt, m0, n0, (s + 2) * KC, K,
                       sb + (uint32_t)((s + 2) % NSTAGE) * STG_BYTES, tid);
        else
            CP_COMMIT();                  // empty group keeps wait counts aligned

        #pragma unroll
        for (int j = 0; j < 4; ++j) {     // four k16 steps per stage
            uint32_t af[2][4], bf[4][4];
            const uint32_t a_co = ((2 * j + a_csel) ^ a_sx) * 16;
            const uint32_t b_co = ((2 * j + b_csel) ^ b_sx) * 16;
            #pragma unroll
            for (int mt = 0; mt < 2; ++mt)
                LDSM4(af[mt], buf + a_base + mt * (16 * 128) + a_co);
            LDSM4(bf[0], buf + b_base + b_co);
            // software-pipelined: LDSM for p+1 issued before MMAs of p
            #pragma unroll
            for (int p = 0; p < 4; ++p) {
                if (p < 3)
                    LDSM4(bf[p + 1], buf + b_base + (p + 1) * (16 * 128) + b_co);
                #pragma unroll
                for (int mt = 0; mt < 2; ++mt) {
                    MMA_F16(acc[mt][2 * p],     af[mt], bf[p][0], bf[p][1]);
                    MMA_F16(acc[mt][2 * p + 1], af[mt], bf[p][2], bf[p][3]);
                }
            }
        }
        // no trailing sync: next stage's barrier fences buffer reuse
    }

    // Epilogue: registers -> gmem with bias
    #pragma unroll
    for (int nt = 0; nt < 8; ++nt) {
        const int col = n0 + wn * 64 + nt * 8 + (lane & 3) * 2;
        const float2 bi = *(const float2*)&bias[col];
        #pragma unroll
        for (int mt = 0; mt < 2; ++mt) {
            const int row = m0 + wm * 32 + mt * 16 + (lane >> 2);
            if (OUT_HALF) {
                __half* C = (__half*)Cv;
                __half2 v0 = __floats2half2_rn(acc[mt][nt][0] + bi.x,
                                               acc[mt][nt][1] + bi.y);
                __half2 v1 = __floats2half2_rn(acc[mt][nt][2] + bi.x,
                                               acc[mt][nt][3] + bi.y);
                *(__half2*)&C[(size_t)row * N + col]       = v0;
                *(__half2*)&C[(size_t)(row + 8) * N + col] = v1;
            } else {
                float* C = (float*)Cv;
                float2 v0 = make_float2(acc[mt][nt][0] + bi.x, acc[mt][nt][1] + bi.y);
                float2 v1 = make_float2(acc[mt][nt][2] + bi.x, acc[mt][nt][3] + bi.y);
                *(float2*)&C[(size_t)row * N + col]       = v0;
                *(float2*)&C[(size_t)(row + 8) * N + col] = v1;
            }
        }
    }
}

// ---------------------------------------------------------------------------
// x -> fp16
// ---------------------------------------------------------------------------
__global__ void xconv_kernel(const float* __restrict__ X, __half* __restrict__ H, int n4)
{
    int i = blockIdx.x * blockDim.x + threadIdx.x;
    if (i >= n4) return;
    float4 v = ((const float4*)X)[i];
    ((__half2*)H)[2 * i]     = __floats2half2_rn(v.x, v.y);
    ((__half2*)H)[2 * i + 1] = __floats2half2_rn(v.z, v.w);
}

// ---------------------------------------------------------------------------
// W[K][N] -> W^T fp16 [N][K]
// ---------------------------------------------------------------------------
__global__ void wconv_kernel(const float* __restrict__ W, __half* __restrict__ Wt,
                             int K, int N)
{
    __shared__ float t[32][33];
    const int nb = blockIdx.x * 32, kb = blockIdx.y * 32;
    const int tx = threadIdx.x, ty = threadIdx.y;   // block (32, 8)
    #pragma unroll
    for (int j = 0; j < 4; ++j)
        t[ty + 8 * j][tx] = W[(size_t)(kb + ty + 8 * j) * N + nb + tx];
    __syncthreads();
    #pragma unroll
    for (int j = 0; j < 4; ++j) {
        int n = nb + ty + 8 * j, k = kb + tx;
        Wt[(size_t)n * K + k] = __float2half_rn(t[tx][ty + 8 * j]);
    }
}

// ---------------------------------------------------------------------------
// Windowed attention. qkv fp16 (half2 loads), math fp32, output fp16.
// ---------------------------------------------------------------------------
__global__ __launch_bounds__(128)
void attn_kernel(const __half* __restrict__ qkv, __half* __restrict__ oh)
{
    const int w = blockIdx.x, h = blockIdx.y, b = blockIdx.z;
    __shared__ float ks[TPW][HD + 1];
    __shared__ float vs[TPW][HD + 1];
    __shared__ float qp[WS][HD + 1];
    __shared__ float at[WS][TPW + 1];

    const int tid = threadIdx.x;
    const size_t base = (size_t)b * NTOK * DIM3;
    const int hoff = h * HD;

    // K, V: 64 tokens x 32 half2 each
    #pragma unroll
    for (int i = 0; i < 16; ++i) {
        int idx = tid + i * 128;          // 0..2047 half2 slots
        int t = idx >> 5, d2 = idx & 31;
        size_t off = base + (size_t)(t * NW + w) * DIM3 + hoff + 2 * d2;
        float2 kv = __half22float2(*(const __half2*)&qkv[off + DIMC]);
        float2 vv = __half22float2(*(const __half2*)&qkv[off + 2 * DIMC]);
        ks[t][2 * d2] = kv.x; ks[t][2 * d2 + 1] = kv.y;
        vs[t][2 * d2] = vv.x; vs[t][2 * d2 + 1] = vv.y;
    }
    // pooled Q: max over 4 strided tokens, half2 loads
    #pragma unroll
    for (int i = 0; i < 4; ++i) {
        int idx = tid + i * 128;          // 0..511 half2 slots
        int qi = idx >> 5, d2 = idx & 31;
        float2 m = make_float2(-3.0e38f, -3.0e38f);
        #pragma unroll
        for (int s = 0; s < 4; ++s) {
            int t = s * WS + qi;
            float2 v = __half22float2(*(const __half2*)
                &qkv[base + (size_t)(t * NW + w) * DIM3 + hoff + 2 * d2]);
            m.x = fmaxf(m.x, v.x); m.y = fmaxf(m.y, v.y);
        }
        qp[qi][2 * d2] = m.x; qp[qi][2 * d2 + 1] = m.y;
    }
    __syncthreads();

    const float scale = 0.125f;
    #pragma unroll
    for (int i = 0; i < 8; ++i) {
        int idx = tid + i * 128;
        int qi = idx >> 6, t = idx & 63;
        float s = 0.f;
        #pragma unroll
        for (int d = 0; d < HD; ++d)
            s = fmaf(qp[qi][d], ks[t][d], s);
        at[qi][t] = s * scale;
    }
    __syncthreads();

    const int lane = tid & 31, wj = tid >> 5;
    for (int r = wj * 4; r < wj * 4 + 4; ++r) {
        float x0 = at[r][lane], x1 = at[r][lane + 32];
        float m = fmaxf(x0, x1);
        #pragma unroll
        for (int o = 16; o; o >>= 1)
            m = fmaxf(m, __shfl_xor_sync(0xffffffffu, m, o));
        float e0 = __expf(x0 - m), e1 = __expf(x1 - m);
        float s = e0 + e1;
        #pragma unroll
        for (int o = 16; o; o >>= 1)
            s += __shfl_xor_sync(0xffffffffu, s, o);
        float inv = 1.f / s;
        at[r][lane]      = e0 * inv;
        at[r][lane + 32] = e1 * inv;
    }
    __syncthreads();

    #pragma unroll
    for (int i = 0; i < 8; ++i) {
        int idx = tid + i * 128;
        int qi = idx >> 6, d = idx & 63;
        float s = 0.f;
        #pragma unroll
        for (int t = 0; t < TPW; ++t)
            s = fmaf(at[qi][t], vs[t][d], s);
        int m = qi * NW + w;
        oh[((size_t)b * MTOK + m) * DIMC + hoff + d] = __float2half_rn(s);
    }
}

// ---------------------------------------------------------------------------
extern "C" void kernel_launch(void* const* d_in, const int* in_sizes, int n_in,
                              void* d_out, int out_size)
{
    const float* x     = (const float*)d_in[0];
    const float* Wqkv  = (const float*)d_in[1];
    const float* bqkv  = (const float*)d_in[2];
    const float* Wproj = (const float*)d_in[3];
    const float* bproj = (const float*)d_in[4];
    float* out = (float*)d_out;

    __half *qkvp, *xh, *oh, *wt;
    cudaGetSymbolAddress((void**)&qkvp, g_qkv);
    cudaGetSymbolAddress((void**)&xh, g_xh);
    cudaGetSymbolAddress((void**)&oh, g_oh);
    cudaGetSymbolAddress((void**)&wt, g_wt);

    cudaFuncSetAttribute(gemm_f16_kernel<0>,
                         cudaFuncAttributeMaxDynamicSharedMemorySize, GEMM_SMEM);
    cudaFuncSetAttribute(gemm_f16_kernel<1>,
                         cudaFuncAttributeMaxDynamicSharedMemorySize, GEMM_SMEM);

    // 0a) x -> fp16
    {
        int n4 = (int)(NELEM_X / 4);
        xconv_kernel<<<n4 / 256, 256>>>(x, xh, n4);
    }
    // 0b) transpose weights -> fp16 [N][K]
    {
        dim3 b(32, 8);
        wconv_kernel<<<dim3(DIM3 / 32, DIMC / 32), b>>>(Wqkv, wt, DIMC, DIM3);
        wconv_kernel<<<dim3(DIMC / 32, DIMC / 32), b>>>(Wproj, wt + WQT_ELEMS,
                                                        DIMC, DIMC);
    }
    // 1) QKV projection -> fp16 qkv
    {
        dim3 grid(DIM3 / TILE_MN, (B_ * NTOK) / TILE_MN);   // (18, 784)
        gemm_f16_kernel<1><<<grid, 256, GEMM_SMEM>>>(xh, wt, bqkv, qkvp,
                                                     B_ * NTOK, DIM3, KDIM);
    }
    // 2) windowed attention with query max-pool
    {
        dim3 grid(NW, HEADS, B_);
        attn_kernel<<<grid, 128>>>(qkvp, oh);
    }
    // 3) output projection -> fp32 out
    {
        dim3 grid(DIMC / TILE_MN, (B_ * MTOK) / TILE_MN);   // (6, 196)
        gemm_f16_kernel<0><<<grid, 256, GEMM_SMEM>>>(oh, wt + WQT_ELEMS,
                                                     bproj, out, B_ * MTOK, DIMC, KDIM);
    }
}